// round 3
// baseline (speedup 1.0000x reference)
#include <cuda_runtime.h>
#include <cuda_bf16.h>

// MySoftBCELoss: B=1048576 rows, C=32 classes, fp32 -> scalar.
//   lp  = x - softplus(x); l1p = -softplus(x); both clamped at log(eps)
//   softplus(x) = max(x,0) + log1p(exp(-|x|))  (MUFU ex2/lg2 path)
//
// Decomposition: 8 threads per row, 1 float4 (4 classes) per thread.
// Coalesced loads, segmented shfl reductions, no smem staging,
// single kernel with last-block-done final reduction.

#define BLOCK 256
#define ROWS_TOTAL 1048576
#define GRID_MAIN (ROWS_TOTAL * 8 / BLOCK)   // 32768
#define NCLS 32

#define LOG_EPS (-16.11809565095832f)         // log(1e-7)

__device__ float g_partials[GRID_MAIN];
__device__ int   g_count = 0;

__global__ void __launch_bounds__(BLOCK) softbce_fused(
    const float4* __restrict__ logits4,
    const float4* __restrict__ target4,
    float* __restrict__ out)
{
    const int tid  = threadIdx.x;
    const int sub  = tid & 7;                  // position within row (0..7)
    const size_t gidx = (size_t)blockIdx.x * BLOCK + tid;  // global float4 index

    // Issue both loads up front (MLP)
    float4 lv = __ldg(logits4 + gidx);
    float4 tv = __ldg(target4 + gidx);

    float xs[4] = {lv.x, lv.y, lv.z, lv.w};
    float ts[4] = {tv.x, tv.y, tv.z, tv.w};

    float sum4  = 0.0f;     // partial soft-BCE sum over my 4 classes
    float tmax  = -1.0f;    // local argmax of target
    int   cmax  = NCLS;     // class index (global within row)
    float lpmax = 0.0f;
    float l1p0  = 0.0f;     // l1p at class 0 (only valid on sub==0)

    #pragma unroll
    for (int k = 0; k < 4; k++) {
        float x = xs[k];
        float t = ts[k];
        float u = fabsf(x);
        float e  = __expf(-u);              // MUFU.EX2 path
        float s0 = __logf(1.0f + e);        // MUFU.LG2 path
        float L  = fmaxf(x, 0.0f) + s0;     // softplus(x)
        float lp  = fmaxf(x - L, LOG_EPS);
        float l1p = fmaxf(-L,    LOG_EPS);
        sum4 += fmaf(t, lp - l1p, l1p);     // t*lp + (1-t)*l1p
        int c = sub * 4 + k;
        if (c == 0) l1p0 = l1p;
        if (t > tmax) { tmax = t; cmax = c; lpmax = lp; }
    }

    // ---- Segmented (width=8) reductions across the row's 8 threads ----
    const unsigned m = 0xFFFFFFFFu;
    #pragma unroll
    for (int o = 4; o > 0; o >>= 1) {
        sum4 += __shfl_xor_sync(m, sum4, o, 8);
        float ot  = __shfl_xor_sync(m, tmax,  o, 8);
        int   oc  = __shfl_xor_sync(m, cmax,  o, 8);
        float olp = __shfl_xor_sync(m, lpmax, o, 8);
        // first-occurrence argmax: bigger t wins; tie -> smaller class index
        if (ot > tmax || (ot == tmax && oc < cmax)) {
            tmax = ot; cmax = oc; lpmax = olp;
        }
    }
    l1p0 = __shfl_sync(m, l1p0, 0, 8);       // broadcast from segment lane 0

    // per-row loss (NEG_WEIGHT = 1); only segment leader keeps it
    float loss = (cmax == 0) ? (sum4 * (1.0f / (float)NCLS))
                             : fmaf(tmax, lpmax, l1p0);
    if (sub != 0) loss = 0.0f;

    // ---- Warp then block reduction ----
    #pragma unroll
    for (int o = 16; o > 0; o >>= 1)
        loss += __shfl_xor_sync(m, loss, o);

    __shared__ float warp_sums[BLOCK / 32];
    if ((tid & 31) == 0) warp_sums[tid >> 5] = loss;
    __syncthreads();

    __shared__ bool is_last;
    if (tid == 0) {
        float b = warp_sums[0];
        #pragma unroll
        for (int w = 1; w < BLOCK / 32; w++) b += warp_sums[w];
        g_partials[blockIdx.x] = b;
        __threadfence();
        int prev = atomicAdd(&g_count, 1);
        is_last = (prev == GRID_MAIN - 1);
    }
    __syncthreads();

    // ---- Last block: deterministic final reduce over all partials ----
    if (is_last) {
        float s = 0.0f;
        #pragma unroll 4
        for (int i = tid; i < GRID_MAIN; i += BLOCK)
            s += g_partials[i];
        #pragma unroll
        for (int o = 16; o > 0; o >>= 1)
            s += __shfl_xor_sync(m, s, o);
        if ((tid & 31) == 0) warp_sums[tid >> 5] = s;
        __syncthreads();
        if (tid == 0) {
            float total = warp_sums[0];
            #pragma unroll
            for (int w = 1; w < BLOCK / 32; w++) total += warp_sums[w];
            out[0] = -total * (1.0f / (float)ROWS_TOTAL);
            g_count = 0;   // reset for next graph replay
        }
    }
}

extern "C" void kernel_launch(void* const* d_in, const int* in_sizes, int n_in,
                              void* d_out, int out_size)
{
    const float4* logits = (const float4*)d_in[0];
    const float4* target = (const float4*)d_in[1];
    float* out = (float*)d_out;

    softbce_fused<<<GRID_MAIN, BLOCK>>>(logits, target, out);
}

// round 6
// speedup vs baseline: 1.4955x; 1.4955x over previous
#include <cuda_runtime.h>
#include <cuda_bf16.h>
#include <cstdint>

// MySoftBCELoss: B=1048576 rows, C=32 classes, fp32 -> scalar.
// Persistent double-buffered cp.async pipeline; 1 thread per row;
// MUFU softplus: lp = x - L, l1p = -L, L = max(x,0)+log1p(exp(-|x|)).

#define BLOCK 64
#define TILE_ROWS 64
#define NCLS 32
#define ROWS_TOTAL 1048576
#define NTILES (ROWS_TOTAL / TILE_ROWS)    // 16384
#define NCTAS (148 * 6)                    // 888 persistent CTAs
#define PITCH4 9                           // float4 per smem row (144 B)
#define T4_PER_TILE (TILE_ROWS * NCLS / 4) // 512 float4 per tensor per tile
#define LOG_EPS (-16.11809565095832f)      // log(1e-7)

__device__ float g_partials[NCTAS];
__device__ int   g_count = 0;

__device__ __forceinline__ void cp_async16(unsigned int saddr, const void* gptr) {
    asm volatile("cp.async.cg.shared.global [%0], [%1], 16;\n"
                 :: "r"(saddr), "l"(gptr));
}
__device__ __forceinline__ void cp_commit() { asm volatile("cp.async.commit_group;\n"); }
__device__ __forceinline__ void cp_wait1()  { asm volatile("cp.async.wait_group 1;\n" ::: "memory"); }

__global__ void __launch_bounds__(BLOCK) softbce_persist(
    const float4* __restrict__ logits4,
    const float4* __restrict__ target4,
    float* __restrict__ out)
{
    // [buf][tensor][row * PITCH4 + q]
    __shared__ float4 sbuf[2][2][TILE_ROWS * PITCH4];   // 36864 B
    __shared__ float  warp_sums[BLOCK / 32];
    __shared__ bool   is_last;

    const int tid = threadIdx.x;

    // Smem byte offsets (relative to sbuf base) for this thread's 8 staged
    // float4 per tensor: fi = tid + it*BLOCK, row = fi>>3, q = fi&7.
    const unsigned int sbase = (unsigned int)__cvta_generic_to_shared(&sbuf[0][0][0]);
    const unsigned int bufStride  = (unsigned int)(2 * TILE_ROWS * PITCH4 * 16);
    const unsigned int tensStride = (unsigned int)(TILE_ROWS * PITCH4 * 16);

    unsigned int soff[8];
    #pragma unroll
    for (int it = 0; it < 8; it++) {
        int fi  = tid + it * BLOCK;
        int row = fi >> 3;
        int q   = fi & 7;
        soff[it] = (unsigned int)((row * PITCH4 + q) * 16);
    }

    float acc = 0.0f;

    // ---- prologue: stage tile blockIdx.x into buf 0 ----
    {
        const size_t gbase = (size_t)blockIdx.x * T4_PER_TILE;
        #pragma unroll
        for (int it = 0; it < 8; it++) {
            int fi = tid + it * BLOCK;
            cp_async16(sbase + soff[it],              logits4 + gbase + fi);
            cp_async16(sbase + tensStride + soff[it], target4 + gbase + fi);
        }
        cp_commit();
    }

    int buf = 0;
    for (int tile = blockIdx.x; tile < NTILES; tile += NCTAS) {
        // stage next tile into other buffer (dummy restage on last iter)
        {
            int next = tile + NCTAS;
            if (next >= NTILES) next = tile;
            const size_t gbase = (size_t)next * T4_PER_TILE;
            const unsigned int bb = sbase + (unsigned int)(buf ^ 1) * bufStride;
            #pragma unroll
            for (int it = 0; it < 8; it++) {
                int fi = tid + it * BLOCK;
                cp_async16(bb + soff[it],              logits4 + gbase + fi);
                cp_async16(bb + tensStride + soff[it], target4 + gbase + fi);
            }
            cp_commit();
        }
        cp_wait1();            // current buffer's group complete
        __syncthreads();

        // ---- compute: thread tid owns row tid of current buffer ----
        const float4* lrow = &sbuf[buf][0][tid * PITCH4];
        const float4* trow = &sbuf[buf][1][tid * PITCH4];

        float sum0  = 0.0f;
        float tmax  = -1.0f;
        int   cmax  = 0;
        float lpmax = 0.0f;
        float l1p0  = 0.0f;

        #pragma unroll
        for (int q = 0; q < 8; q++) {
            float4 lv = lrow[q];
            float4 tv = trow[q];
            float xs[4] = {lv.x, lv.y, lv.z, lv.w};
            float ts[4] = {tv.x, tv.y, tv.z, tv.w};
            #pragma unroll
            for (int k = 0; k < 4; k++) {
                float x = xs[k];
                float t = ts[k];
                float u = fabsf(x);
                float e  = __expf(-u);             // MUFU.EX2 path
                float s0 = __logf(1.0f + e);       // MUFU.LG2 path
                float L  = fmaxf(x, 0.0f) + s0;    // softplus(x)
                float lp  = fmaxf(x - L, LOG_EPS);
                float l1p = fmaxf(-L,    LOG_EPS);
                sum0 += fmaf(t, lp - l1p, l1p);    // t*lp + (1-t)*l1p
                int c = q * 4 + k;
                if (c == 0) l1p0 = l1p;
                if (t > tmax) { tmax = t; cmax = c; lpmax = lp; }
            }
        }

        acc += (cmax == 0) ? (sum0 * (1.0f / (float)NCLS))
                           : fmaf(tmax, lpmax, l1p0);

        __syncthreads();       // protect buf before next iteration's restage
        buf ^= 1;
    }

    // ---- block reduction (2 warps) ----
    const unsigned m = 0xFFFFFFFFu;
    #pragma unroll
    for (int o = 16; o > 0; o >>= 1)
        acc += __shfl_xor_sync(m, acc, o);
    if ((tid & 31) == 0) warp_sums[tid >> 5] = acc;
    __syncthreads();

    if (tid == 0) {
        g_partials[blockIdx.x] = warp_sums[0] + warp_sums[1];
        __threadfence();
        int prev = atomicAdd(&g_count, 1);
        is_last = (prev == NCTAS - 1);
    }
    __syncthreads();

    // ---- last CTA: deterministic final reduce ----
    if (is_last) {
        float s = 0.0f;
        for (int i = tid; i < NCTAS; i += BLOCK)
            s += g_partials[i];
        #pragma unroll
        for (int o = 16; o > 0; o >>= 1)
            s += __shfl_xor_sync(m, s, o);
        if ((tid & 31) == 0) warp_sums[tid >> 5] = s;
        __syncthreads();
        if (tid == 0) {
            out[0] = -(warp_sums[0] + warp_sums[1]) * (1.0f / (float)ROWS_TOTAL);
            g_count = 0;   // reset for next graph replay
        }
    }
}

extern "C" void kernel_launch(void* const* d_in, const int* in_sizes, int n_in,
                              void* d_out, int out_size)
{
    const float4* logits = (const float4*)d_in[0];
    const float4* target = (const float4*)d_in[1];
    float* out = (float*)d_out;

    softbce_persist<<<NCTAS, BLOCK>>>(logits, target, out);
}

// round 7
// speedup vs baseline: 1.5952x; 1.0667x over previous
#include <cuda_runtime.h>
#include <cuda_bf16.h>
#include <cstdint>

// MySoftBCELoss: B=1048576 rows, C=32 classes, fp32 -> scalar.
// Persistent double-buffered cp.async pipeline.
// 2 threads per row (16 classes each), width-2 shuffle combine.
// MUFU softplus: lp = x - L, l1p = -L, L = max(x,0)+log1p(exp(-|x|)).

#define BLOCK 128
#define TILE_ROWS 64
#define NCLS 32
#define ROWS_TOTAL 1048576
#define NTILES (ROWS_TOTAL / TILE_ROWS)    // 16384
#define NCTAS (148 * 6)                    // 888 persistent CTAs
#define PITCH4 9                           // float4 per smem row (144 B)
#define T4_PER_TILE (TILE_ROWS * NCLS / 4) // 512 float4 per tensor per tile
#define LOG_EPS (-16.11809565095832f)      // log(1e-7)

__device__ float g_partials[NCTAS];
__device__ int   g_count = 0;

__device__ __forceinline__ void cp_async16(unsigned int saddr, const void* gptr) {
    asm volatile("cp.async.cg.shared.global [%0], [%1], 16;\n"
                 :: "r"(saddr), "l"(gptr));
}
__device__ __forceinline__ void cp_commit() { asm volatile("cp.async.commit_group;\n"); }
__device__ __forceinline__ void cp_wait1()  { asm volatile("cp.async.wait_group 1;\n" ::: "memory"); }
__device__ __forceinline__ void cp_wait0()  { asm volatile("cp.async.wait_group 0;\n" ::: "memory"); }

__global__ void __launch_bounds__(BLOCK) softbce_persist(
    const float4* __restrict__ logits4,
    const float4* __restrict__ target4,
    float* __restrict__ out)
{
    // [buf][tensor][row * PITCH4 + q]
    __shared__ float4 sbuf[2][2][TILE_ROWS * PITCH4];   // 36864 B
    __shared__ float  warp_sums[BLOCK / 32];
    __shared__ bool   is_last;

    const int tid  = threadIdx.x;
    const int row  = tid >> 1;          // 0..63
    const int half = tid & 1;           // 0: cols 0-15, 1: cols 16-31

    const unsigned int sbase = (unsigned int)__cvta_generic_to_shared(&sbuf[0][0][0]);
    const unsigned int bufStride  = (unsigned int)(2 * TILE_ROWS * PITCH4 * 16);
    const unsigned int tensStride = (unsigned int)(TILE_ROWS * PITCH4 * 16);

    // staging offsets: fi = tid + it*BLOCK (0..511), srow = fi>>3, q = fi&7
    unsigned int soff[4];
    #pragma unroll
    for (int it = 0; it < 4; it++) {
        int fi   = tid + it * BLOCK;
        int srow = fi >> 3;
        int q    = fi & 7;
        soff[it] = (unsigned int)((srow * PITCH4 + q) * 16);
    }

    float acc = 0.0f;
    const unsigned m = 0xFFFFFFFFu;

    // ---- prologue: stage tile blockIdx.x into buf 0 ----
    {
        const size_t gbase = (size_t)blockIdx.x * T4_PER_TILE;
        #pragma unroll
        for (int it = 0; it < 4; it++) {
            int fi = tid + it * BLOCK;
            cp_async16(sbase + soff[it],              logits4 + gbase + fi);
            cp_async16(sbase + tensStride + soff[it], target4 + gbase + fi);
        }
        cp_commit();
    }

    int buf = 0;
    for (int tile = blockIdx.x; tile < NTILES; tile += NCTAS) {
        // stage next tile into other buffer (skip on final iteration)
        int next = tile + NCTAS;
        if (next < NTILES) {
            const size_t gbase = (size_t)next * T4_PER_TILE;
            const unsigned int bb = sbase + (unsigned int)(buf ^ 1) * bufStride;
            #pragma unroll
            for (int it = 0; it < 4; it++) {
                int fi = tid + it * BLOCK;
                cp_async16(bb + soff[it],              logits4 + gbase + fi);
                cp_async16(bb + tensStride + soff[it], target4 + gbase + fi);
            }
            cp_commit();
            cp_wait1();        // current buffer complete, next still in flight
        } else {
            cp_wait0();        // final tile: drain everything
        }
        __syncthreads();

        // ---- compute: thread owns 16 classes of its row ----
        const float4* lrow = &sbuf[buf][0][row * PITCH4 + half * 4];
        const float4* trow = &sbuf[buf][1][row * PITCH4 + half * 4];

        float psum  = 0.0f;    // partial soft-BCE sum (16 classes)
        float tmax  = -1.0f;
        int   cmax  = NCLS;
        float lpmax = 0.0f;
        float l1p0  = 0.0f;    // valid on half==0

        #pragma unroll
        for (int q = 0; q < 4; q++) {
            float4 lv = lrow[q];
            float4 tv = trow[q];
            float xs[4] = {lv.x, lv.y, lv.z, lv.w};
            float ts[4] = {tv.x, tv.y, tv.z, tv.w};
            #pragma unroll
            for (int k = 0; k < 4; k++) {
                float x = xs[k];
                float t = ts[k];
                float u = fabsf(x);
                float e  = __expf(-u);             // MUFU.EX2 path
                float s0 = __logf(1.0f + e);       // MUFU.LG2 path
                float L  = fmaxf(x, 0.0f) + s0;    // softplus(x)
                float lp  = fmaxf(x - L, LOG_EPS);
                float l1p = fmaxf(-L,    LOG_EPS);
                psum += fmaf(t, lp - l1p, l1p);    // t*lp + (1-t)*l1p
                int c = half * 16 + q * 4 + k;
                if (c == 0) l1p0 = l1p;
                if (t > tmax) { tmax = t; cmax = c; lpmax = lp; }
            }
        }

        // ---- width-2 combine across the row's two threads ----
        psum += __shfl_xor_sync(m, psum, 1, 2);
        {
            float ot  = __shfl_xor_sync(m, tmax,  1, 2);
            int   oc  = __shfl_xor_sync(m, cmax,  1, 2);
            float olp = __shfl_xor_sync(m, lpmax, 1, 2);
            if (ot > tmax || (ot == tmax && oc < cmax)) {
                tmax = ot; cmax = oc; lpmax = olp;
            }
        }
        l1p0 = __shfl_sync(m, l1p0, 0, 2);   // from even lane

        if (half == 0) {
            acc += (cmax == 0) ? (psum * (1.0f / (float)NCLS))
                               : fmaf(tmax, lpmax, l1p0);
        }

        __syncthreads();     // protect buf before next iteration's restage
        buf ^= 1;
    }

    // ---- block reduction (4 warps) ----
    #pragma unroll
    for (int o = 16; o > 0; o >>= 1)
        acc += __shfl_xor_sync(m, acc, o);
    if ((tid & 31) == 0) warp_sums[tid >> 5] = acc;
    __syncthreads();

    if (tid == 0) {
        g_partials[blockIdx.x] = warp_sums[0] + warp_sums[1]
                               + warp_sums[2] + warp_sums[3];
        __threadfence();
        int prev = atomicAdd(&g_count, 1);
        is_last = (prev == NCTAS - 1);
    }
    __syncthreads();

    // ---- last CTA: deterministic final reduce ----
    if (is_last) {
        float s = 0.0f;
        for (int i = tid; i < NCTAS; i += BLOCK)
            s += g_partials[i];
        #pragma unroll
        for (int o = 16; o > 0; o >>= 1)
            s += __shfl_xor_sync(m, s, o);
        if ((tid & 31) == 0) warp_sums[tid >> 5] = s;
        __syncthreads();
        if (tid == 0) {
            out[0] = -(warp_sums[0] + warp_sums[1] + warp_sums[2] + warp_sums[3])
                     * (1.0f / (float)ROWS_TOTAL);
            g_count = 0;   // reset for next graph replay
        }
    }
}

extern "C" void kernel_launch(void* const* d_in, const int* in_sizes, int n_in,
                              void* d_out, int out_size)
{
    const float4* logits = (const float4*)d_in[0];
    const float4* target = (const float4*)d_in[1];
    float* out = (float*)d_out;

    softbce_persist<<<NCTAS, BLOCK>>>(logits, target, out);
}

// round 8
// speedup vs baseline: 1.6086x; 1.0084x over previous
#include <cuda_runtime.h>
#include <cuda_bf16.h>
#include <cstdint>

// MySoftBCELoss: B=1048576 rows, C=32 classes, fp32 -> scalar.
// Warp-autonomous persistent pipelines: each warp double-buffers its own
// 16-row tile via cp.async; no block barriers in the steady state.
// 2 threads/row (16 classes each); MUFU softplus.

#define BLOCK 128
#define WARPS (BLOCK / 32)                  // 4
#define TILE_ROWS 16                        // rows per warp-tile
#define NCLS 32
#define ROWS_TOTAL 1048576
#define NTILES (ROWS_TOTAL / TILE_ROWS)     // 65536
#define NCTAS (148 * 6)                     // 888 persistent CTAs
#define TOTAL_WARPS (NCTAS * WARPS)         // 3552
#define PITCH4 9                            // float4 per smem row (144 B)
#define T4_PER_TILE (TILE_ROWS * NCLS / 4)  // 128 float4 per tensor per tile
#define WBUF4 (TILE_ROWS * PITCH4)          // 144 float4 per tensor per buf
#define LOG_EPS (-16.11809565095832f)       // log(1e-7)

__device__ float g_partials[NCTAS];
__device__ int   g_count = 0;

__device__ __forceinline__ void cp_async16(unsigned int saddr, const void* gptr) {
    asm volatile("cp.async.cg.shared.global [%0], [%1], 16;\n"
                 :: "r"(saddr), "l"(gptr));
}
__device__ __forceinline__ void cp_commit() { asm volatile("cp.async.commit_group;\n"); }
__device__ __forceinline__ void cp_wait1()  { asm volatile("cp.async.wait_group 1;\n" ::: "memory"); }
__device__ __forceinline__ void cp_wait0()  { asm volatile("cp.async.wait_group 0;\n" ::: "memory"); }

__global__ void __launch_bounds__(BLOCK) softbce_warp(
    const float4* __restrict__ logits4,
    const float4* __restrict__ target4,
    float* __restrict__ out)
{
    // [warp][buf][tensor][row * PITCH4 + q]
    __shared__ float4 sbuf[WARPS][2][2][WBUF4];   // 4*2*2*144*16 = 36864 B
    __shared__ float  warp_sums[WARPS];
    __shared__ bool   is_last;

    const int tid  = threadIdx.x;
    const int wid  = tid >> 5;
    const int lane = tid & 31;
    const int row  = lane >> 1;          // 0..15
    const int half = lane & 1;           // 0: cols 0-15, 1: cols 16-31
    const unsigned m = 0xFFFFFFFFu;

    const int gwarp = blockIdx.x * WARPS + wid;   // 0..3551

    // smem shared-space base for this warp
    const unsigned int wbase =
        (unsigned int)__cvta_generic_to_shared(&sbuf[wid][0][0][0]);
    const unsigned int bufStride  = (unsigned int)(2 * WBUF4 * 16);  // per buf
    const unsigned int tensStride = (unsigned int)(WBUF4 * 16);      // per tensor

    // staging smem offsets: fi = lane + it*32 (0..127), srow=fi>>3, q=fi&7
    unsigned int soff[4];
    #pragma unroll
    for (int it = 0; it < 4; it++) {
        int fi   = lane + it * 32;
        int srow = fi >> 3;
        int q    = fi & 7;
        soff[it] = (unsigned int)((srow * PITCH4 + q) * 16);
    }

    float acc = 0.0f;

    // ---- prologue: stage tile gwarp into buf 0 ----
    {
        const size_t gbase = (size_t)gwarp * T4_PER_TILE;
        #pragma unroll
        for (int it = 0; it < 4; it++) {
            int fi = lane + it * 32;
            cp_async16(wbase + soff[it],              logits4 + gbase + fi);
            cp_async16(wbase + tensStride + soff[it], target4 + gbase + fi);
        }
        cp_commit();
    }

    int buf = 0;
    for (int tile = gwarp; tile < NTILES; tile += TOTAL_WARPS) {
        // stage next tile into the other buffer (none on final iteration)
        int next = tile + TOTAL_WARPS;
        if (next < NTILES) {
            const size_t gbase = (size_t)next * T4_PER_TILE;
            const unsigned int bb = wbase + (unsigned int)(buf ^ 1) * bufStride;
            #pragma unroll
            for (int it = 0; it < 4; it++) {
                int fi = lane + it * 32;
                cp_async16(bb + soff[it],              logits4 + gbase + fi);
                cp_async16(bb + tensStride + soff[it], target4 + gbase + fi);
            }
            cp_commit();
            cp_wait1();          // current buffer's group complete
        } else {
            cp_wait0();
        }
        __syncwarp(m);           // cross-lane visibility of staged data

        // ---- compute: 2 lanes per row, 16 classes each ----
        const float4* lrow = &sbuf[wid][buf][0][row * PITCH4 + half * 4];
        const float4* trow = &sbuf[wid][buf][1][row * PITCH4 + half * 4];

        float psum  = 0.0f;
        float tmax  = -1.0f;
        int   cmax  = NCLS;
        float lpmax = 0.0f;
        float l1p0  = 0.0f;      // valid on half==0

        #pragma unroll
        for (int q = 0; q < 4; q++) {
            float4 lv = lrow[q];
            float4 tv = trow[q];
            float xs[4] = {lv.x, lv.y, lv.z, lv.w};
            float ts[4] = {tv.x, tv.y, tv.z, tv.w};
            #pragma unroll
            for (int k = 0; k < 4; k++) {
                float x = xs[k];
                float t = ts[k];
                float u = fabsf(x);
                float e  = __expf(-u);             // MUFU.EX2 path
                float s0 = __logf(1.0f + e);       // MUFU.LG2 path
                float L  = fmaxf(x, 0.0f) + s0;    // softplus(x)
                float lp  = fmaxf(x - L, LOG_EPS);
                float l1p = fmaxf(-L,    LOG_EPS);
                psum += fmaf(t, lp - l1p, l1p);    // t*lp + (1-t)*l1p
                int c = half * 16 + q * 4 + k;
                if (c == 0) l1p0 = l1p;
                if (t > tmax) { tmax = t; cmax = c; lpmax = lp; }
            }
        }

        // ---- width-2 combine across the row's two lanes ----
        psum += __shfl_xor_sync(m, psum, 1, 2);
        {
            float ot  = __shfl_xor_sync(m, tmax,  1, 2);
            int   oc  = __shfl_xor_sync(m, cmax,  1, 2);
            float olp = __shfl_xor_sync(m, lpmax, 1, 2);
            if (ot > tmax || (ot == tmax && oc < cmax)) {
                tmax = ot; cmax = oc; lpmax = olp;
            }
        }
        l1p0 = __shfl_sync(m, l1p0, 0, 2);   // from even lane of the pair

        if (half == 0) {
            acc += (cmax == 0) ? (psum * (1.0f / (float)NCLS))
                               : fmaf(tmax, lpmax, l1p0);
        }

        __syncwarp(m);           // all lanes done with buf before restage
        buf ^= 1;
    }

    // ---- warp reduce (odd lanes hold 0) ----
    #pragma unroll
    for (int o = 16; o > 0; o >>= 1)
        acc += __shfl_xor_sync(m, acc, o);
    if (lane == 0) warp_sums[wid] = acc;
    __syncthreads();

    if (tid == 0) {
        g_partials[blockIdx.x] = warp_sums[0] + warp_sums[1]
                               + warp_sums[2] + warp_sums[3];
        __threadfence();
        int prev = atomicAdd(&g_count, 1);
        is_last = (prev == NCTAS - 1);
    }
    __syncthreads();

    // ---- last CTA: deterministic final reduce ----
    if (is_last) {
        float s = 0.0f;
        for (int i = tid; i < NCTAS; i += BLOCK)
            s += g_partials[i];
        #pragma unroll
        for (int o = 16; o > 0; o >>= 1)
            s += __shfl_xor_sync(m, s, o);
        if ((tid & 31) == 0) warp_sums[tid >> 5] = s;
        __syncthreads();
        if (tid == 0) {
            out[0] = -(warp_sums[0] + warp_sums[1] + warp_sums[2] + warp_sums[3])
                     * (1.0f / (float)ROWS_TOTAL);
            g_count = 0;   // reset for next graph replay
        }
    }
}

extern "C" void kernel_launch(void* const* d_in, const int* in_sizes, int n_in,
                              void* d_out, int out_size)
{
    const float4* logits = (const float4*)d_in[0];
    const float4* target = (const float4*)d_in[1];
    float* out = (float*)d_out;

    softbce_warp<<<NCTAS, BLOCK>>>(logits, target, out);
}